// round 1
// baseline (speedup 1.0000x reference)
#include <cuda_runtime.h>
#include <cuda_bf16.h>
#include <cstdint>

// Sparsemax over rows of [B=2048, V=32000] fp32.
// One CTA per row. Row lives in registers (1024 thr x 8 float4).
// tau found exactly via Michelot's algorithm on candidates >= rowmax - 1
// (sparsemax support provably lies in [rowmax-1, rowmax]).

#define THREADS 1024
#define VROW 32000
#define V4ROW (VROW / 4)          // 8000 float4 per row
#define PER_THREAD 8              // 8 float4 slots per thread (capacity 8192)
#define NEG_INF (-3.4e38f)

// dynamic smem: candidate buffer, worst case all VROW elements fit -> no overflow path
#define SMEM_BYTES (VROW * (int)sizeof(float))

__global__ __launch_bounds__(THREADS, 1)
void sparsemax_kernel(const float* __restrict__ in, float* __restrict__ out)
{
    extern __shared__ float cand[];                 // [VROW]
    __shared__ float s_red[32];
    __shared__ float s_max;
    __shared__ float s_tau;
    __shared__ int   s_num;

    const int tid  = threadIdx.x;
    const int lane = tid & 31;
    const int wid  = tid >> 5;
    const unsigned FULL = 0xffffffffu;
    const unsigned lmask_lt = (1u << lane) - 1u;

    const size_t row_off = (size_t)blockIdx.x * VROW;
    const float4* __restrict__ inrow  = (const float4*)(in  + row_off);
    float4*       __restrict__ outrow = (float4*)(out + row_off);

    if (tid == 0) s_num = 0;

    // ---- load row into registers, compute local max ----
    float4 v[PER_THREAD];
    float lmax = NEG_INF;
#pragma unroll
    for (int i = 0; i < PER_THREAD; ++i) {
        int idx = tid + i * THREADS;
        if (idx < V4ROW) {
            v[i] = inrow[idx];
        } else {
            v[i] = make_float4(NEG_INF, NEG_INF, NEG_INF, NEG_INF);
        }
        lmax = fmaxf(lmax, fmaxf(fmaxf(v[i].x, v[i].y), fmaxf(v[i].z, v[i].w)));
    }

    // ---- block max reduction ----
#pragma unroll
    for (int off = 16; off; off >>= 1)
        lmax = fmaxf(lmax, __shfl_xor_sync(FULL, lmax, off));
    if (lane == 0) s_red[wid] = lmax;
    __syncthreads();
    if (wid == 0) {
        float m = s_red[lane];   // exactly 32 warps
#pragma unroll
        for (int off = 16; off; off >>= 1)
            m = fmaxf(m, __shfl_xor_sync(FULL, m, off));
        if (lane == 0) s_max = m;
    }
    __syncthreads();

    const float rmax = s_max;
    // support of sparsemax is strictly above rmax - 1; small slack for fp32 rounding
    const float thr = rmax - 1.001f;

    // ---- warp-aggregated compaction of candidates into shared (shifted by -rmax) ----
#pragma unroll
    for (int i = 0; i < PER_THREAD; ++i) {
        float c[4] = {v[i].x, v[i].y, v[i].z, v[i].w};
#pragma unroll
        for (int j = 0; j < 4; ++j) {
            float x = c[j];
            bool p = (x >= thr);
            unsigned m = __ballot_sync(FULL, p);
            if (m) {
                int leader = __ffs(m) - 1;
                int base = 0;
                if (lane == leader) base = atomicAdd(&s_num, __popc(m));
                base = __shfl_sync(FULL, base, leader);
                if (p) {
                    int pos = base + __popc(m & lmask_lt);
                    cand[pos] = x - rmax;       // in [-1.001, 0]
                }
            }
        }
    }
    __syncthreads();

    // ---- warp 0: Michelot's algorithm (exact sparsemax threshold) ----
    if (wid == 0) {
        const int n = s_num;
        float t = -2.0f;          // below all candidates -> first pass counts all
        int prev = -1;
        for (int it = 0; it < n + 2; ++it) {
            float sum = 0.0f;
            int cnt = 0;
            for (int i = lane; i < n; i += 32) {
                float x = cand[i];
                if (x > t) { sum += x; cnt++; }
            }
#pragma unroll
            for (int off = 16; off; off >>= 1) {
                sum += __shfl_xor_sync(FULL, sum, off);
                cnt += __shfl_xor_sync(FULL, cnt, off);
            }
            if (cnt == prev) break;   // active set stable -> t is the fixed point
            prev = cnt;
            t = (sum - 1.0f) / (float)cnt;
        }
        if (lane == 0) s_tau = t;
    }
    __syncthreads();

    const float tau = rmax + s_tau;

    // ---- emit max(x - tau, 0) from registers ----
#pragma unroll
    for (int i = 0; i < PER_THREAD; ++i) {
        int idx = tid + i * THREADS;
        if (idx < V4ROW) {
            float4 r;
            r.x = fmaxf(v[i].x - tau, 0.0f);
            r.y = fmaxf(v[i].y - tau, 0.0f);
            r.z = fmaxf(v[i].z - tau, 0.0f);
            r.w = fmaxf(v[i].w - tau, 0.0f);
            outrow[idx] = r;
        }
    }
}

extern "C" void kernel_launch(void* const* d_in, const int* in_sizes, int n_in,
                              void* d_out, int out_size)
{
    const float* in = (const float*)d_in[0];
    float* out = (float*)d_out;
    int B = out_size / VROW;

    cudaFuncSetAttribute(sparsemax_kernel,
                         cudaFuncAttributeMaxDynamicSharedMemorySize, SMEM_BYTES);
    sparsemax_kernel<<<B, THREADS, SMEM_BYTES>>>(in, out);
}